// round 3
// baseline (speedup 1.0000x reference)
#include <cuda_runtime.h>

// Geometry (fixed by the problem)
#define B_    4
#define CIN_  8
#define H_    64
#define W_    64
#define COUT_ 32
#define KH_   3
#define KW_   3
#define K_    72      // CIN*KH*KW
#define L_    4096    // HO*WO
#define HO_   64
#define WO_   64
#define POT_ELEMS (B_*COUT_*L_)          // 524288
#define ROWS_PER_BLK 8                    // 512 l-values per block
#define THREADS 128

__global__ __launch_bounds__(THREADS, 6)
void conv2d_expdelay_kernel(
    const float* __restrict__ x,          // [B, CIN, H, W]
    const float* __restrict__ weight,     // [COUT, K]
    const float* __restrict__ trace,      // [B, COUT, K, L]
    const float* __restrict__ delay,      // [B, COUT, K, L]
    const float* __restrict__ dinit,      // [B, COUT, K, L]
    const float* __restrict__ p_alpha,
    const float* __restrict__ p_tau,
    const float* __restrict__ p_dt,
    float* __restrict__ out)              // [pot | trace_new]
{
    // smem x tile: CIN x (ROWS+2) x (WO+2), cols padded to 68 vs bank conflicts
    __shared__ float xs[CIN_][ROWS_PER_BLK + 2][68];
    __shared__ float ws[K_];

    const int bo  = blockIdx.y;           // b*COUT + o
    const int o   = bo & (COUT_ - 1);
    const int b   = bo >> 5;
    const int row0 = blockIdx.x * ROWS_PER_BLK;   // ho base of this tile
    const int tid  = threadIdx.x;

    if (tid < K_) ws[tid] = weight[o * K_ + tid];

    // Load padded x tile: 8 * 10 * 66 = 5280 elements
    for (int i = tid; i < CIN_ * (ROWS_PER_BLK + 2) * 66; i += THREADS) {
        int c   = i / ((ROWS_PER_BLK + 2) * 66);
        int rem = i % ((ROWS_PER_BLK + 2) * 66);
        int r   = rem / 66;
        int col = rem % 66;
        int gh = row0 + r - 1;
        int gw = col - 1;
        float v = 0.0f;
        if (gh >= 0 && gh < H_ && gw >= 0 && gw < W_)
            v = x[((b * CIN_ + c) * H_ + gh) * W_ + gw];
        xs[c][r][col] = v;
    }
    __syncthreads();

    const float alpha = *p_alpha;
    const float coeff = (*p_dt) / (*p_tau);

    const int l0   = blockIdx.x * (ROWS_PER_BLK * WO_) + tid * 4;  // global l
    const int lrow = (tid * 4) >> 6;     // row within tile (0..7)
    const int wo   = (tid * 4) & 63;

    const size_t base_bo = (size_t)bo * K_ * L_;
    float* __restrict__ trout = out + POT_ELEMS;

    float4 pot = make_float4(0.f, 0.f, 0.f, 0.f);

    // Software pipeline: keep next iteration's three streams in flight while
    // computing the current one.
    size_t idx0 = base_bo + (size_t)l0;
    float4 t4 = *reinterpret_cast<const float4*>(trace + idx0);
    float4 d4 = *reinterpret_cast<const float4*>(delay + idx0);
    float4 i4 = *reinterpret_cast<const float4*>(dinit + idx0);

    #pragma unroll
    for (int k = 0; k < K_; ++k) {
        const int c  = k / 9;
        const int kh = (k % 9) / 3;
        const int kw = k % 3;

        float4 tnx, dnx, inx;
        if (k + 1 < K_) {
            const size_t idxn = base_bo + (size_t)(k + 1) * L_ + l0;
            tnx = *reinterpret_cast<const float4*>(trace + idxn);
            dnx = *reinterpret_cast<const float4*>(delay + idxn);
            inx = *reinterpret_cast<const float4*>(dinit + idxn);
        }

        const float* xrow = &xs[c][lrow + kh][wo + kw];
        const float xu0 = xrow[0];
        const float xu1 = xrow[1];
        const float xu2 = xrow[2];
        const float xu3 = xrow[3];

        // trace_new = trace + coeff*(alpha*xu - trace)
        float4 tn;
        tn.x = fmaf(coeff, fmaf(alpha, xu0, -t4.x), t4.x);
        tn.y = fmaf(coeff, fmaf(alpha, xu1, -t4.y), t4.y);
        tn.z = fmaf(coeff, fmaf(alpha, xu2, -t4.z), t4.z);
        tn.w = fmaf(coeff, fmaf(alpha, xu3, -t4.w), t4.w);
        const size_t idx = base_bo + (size_t)k * L_ + l0;
        *reinterpret_cast<float4*>(trout + idx) = tn;

        // spike = (delay + xu*delay_init == 1.0f); pot += spike * w
        const float w = ws[k];
        pot.x += (fmaf(xu0, i4.x, d4.x) == 1.0f) ? w : 0.0f;
        pot.y += (fmaf(xu1, i4.y, d4.y) == 1.0f) ? w : 0.0f;
        pot.z += (fmaf(xu2, i4.z, d4.z) == 1.0f) ? w : 0.0f;
        pot.w += (fmaf(xu3, i4.w, d4.w) == 1.0f) ? w : 0.0f;

        t4 = tnx; d4 = dnx; i4 = inx;
    }

    *reinterpret_cast<float4*>(out + (size_t)bo * L_ + l0) = pot;
}

extern "C" void kernel_launch(void* const* d_in, const int* in_sizes, int n_in,
                              void* d_out, int out_size) {
    const float* x      = (const float*)d_in[0];
    const float* weight = (const float*)d_in[1];
    const float* trace  = (const float*)d_in[2];
    const float* delay  = (const float*)d_in[3];
    const float* dinit  = (const float*)d_in[4];
    const float* alpha  = (const float*)d_in[5];
    const float* tau    = (const float*)d_in[6];
    const float* dt     = (const float*)d_in[7];
    float* out = (float*)d_out;

    dim3 grid(L_ / (ROWS_PER_BLK * WO_), B_ * COUT_);   // (8, 128)
    conv2d_expdelay_kernel<<<grid, THREADS>>>(x, weight, trace, delay, dinit,
                                              alpha, tau, dt, out);
}

// round 4
// speedup vs baseline: 1.0524x; 1.0524x over previous
#include <cuda_runtime.h>

// Geometry (fixed by the problem)
#define B_    4
#define CIN_  8
#define H_    64
#define W_    64
#define COUT_ 32
#define KH_   3
#define KW_   3
#define K_    72      // CIN*KH*KW
#define L_    4096    // HO*WO
#define HO_   64
#define WO_   64
#define POT_ELEMS (B_*COUT_*L_)          // 524288
#define ROWS_PER_BLK 16                   // 1024 l-values per block
#define THREADS 256
#define XTILE_ROW 68                      // padded row width
#define XTILE_PLANE ((ROWS_PER_BLK + 2) * XTILE_ROW)

__global__ __launch_bounds__(THREADS, 2)
void conv2d_expdelay_kernel(
    const float* __restrict__ x,          // [B, CIN, H, W]
    const float* __restrict__ weight,     // [COUT, K]
    const float* __restrict__ trace,      // [B, COUT, K, L]
    const float* __restrict__ delay,      // [B, COUT, K, L]
    const float* __restrict__ dinit,      // [B, COUT, K, L]
    const float* __restrict__ p_alpha,
    const float* __restrict__ p_tau,
    const float* __restrict__ p_dt,
    float* __restrict__ out)              // [pot | trace_new]
{
    __shared__ float xs[CIN_ * XTILE_PLANE];   // 8*18*68 = 9792 floats
    __shared__ float ws[K_];
    __shared__ int   xoff[K_];                 // per-k offset into xs

    const int bo  = blockIdx.y;           // b*COUT + o
    const int o   = bo & (COUT_ - 1);
    const int b   = bo >> 5;
    const int row0 = blockIdx.x * ROWS_PER_BLK;
    const int tid  = threadIdx.x;

    if (tid < K_) {
        ws[tid] = weight[o * K_ + tid];
        const int c  = tid / 9;
        const int kh = (tid % 9) / 3;
        const int kw = tid % 3;
        xoff[tid] = c * XTILE_PLANE + kh * XTILE_ROW + kw;
    }

    // Load padded x tile: 8 * 18 * 66 valid elements
    for (int i = tid; i < CIN_ * (ROWS_PER_BLK + 2) * 66; i += THREADS) {
        int c   = i / ((ROWS_PER_BLK + 2) * 66);
        int rem = i % ((ROWS_PER_BLK + 2) * 66);
        int r   = rem / 66;
        int col = rem % 66;
        int gh = row0 + r - 1;
        int gw = col - 1;
        float v = 0.0f;
        if (gh >= 0 && gh < H_ && gw >= 0 && gw < W_)
            v = x[((b * CIN_ + c) * H_ + gh) * W_ + gw];
        xs[c * XTILE_PLANE + r * XTILE_ROW + col] = v;
    }
    __syncthreads();

    const float alpha = *p_alpha;
    const float coeff = (*p_dt) / (*p_tau);

    const int l0   = blockIdx.x * (ROWS_PER_BLK * WO_) + tid * 4;  // global l
    const int lrow = (tid * 4) >> 6;     // row within tile (0..15)
    const int wo   = (tid * 4) & 63;
    const int xbase = lrow * XTILE_ROW + wo;   // thread's base into xs

    const size_t base = (size_t)bo * K_ * L_ + l0;
    float* __restrict__ trout = out + POT_ELEMS;

    float4 pot = make_float4(0.f, 0.f, 0.f, 0.f);

    #pragma unroll 1
    for (int kb = 0; kb < K_; kb += 4) {
        // Front-batch all 12 wide loads for 4 k-steps (MLP depth 12).
        float4 t4[4], d4[4], i4[4];
        #pragma unroll
        for (int j = 0; j < 4; ++j) {
            const size_t idx = base + (size_t)(kb + j) * L_;
            t4[j] = *reinterpret_cast<const float4*>(trace + idx);
            d4[j] = *reinterpret_cast<const float4*>(delay + idx);
            i4[j] = *reinterpret_cast<const float4*>(dinit + idx);
        }

        #pragma unroll
        for (int j = 0; j < 4; ++j) {
            const int k = kb + j;
            const float* xrow = xs + xbase + xoff[k];
            const float xu0 = xrow[0];
            const float xu1 = xrow[1];
            const float xu2 = xrow[2];
            const float xu3 = xrow[3];

            // trace_new = trace + coeff*(alpha*xu - trace)
            float4 tn;
            tn.x = fmaf(coeff, fmaf(alpha, xu0, -t4[j].x), t4[j].x);
            tn.y = fmaf(coeff, fmaf(alpha, xu1, -t4[j].y), t4[j].y);
            tn.z = fmaf(coeff, fmaf(alpha, xu2, -t4[j].z), t4[j].z);
            tn.w = fmaf(coeff, fmaf(alpha, xu3, -t4[j].w), t4[j].w);
            *reinterpret_cast<float4*>(trout + base + (size_t)k * L_) = tn;

            // spike = (delay + xu*delay_init == 1.0f); pot += spike * w
            const float w = ws[k];
            pot.x += (fmaf(xu0, i4[j].x, d4[j].x) == 1.0f) ? w : 0.0f;
            pot.y += (fmaf(xu1, i4[j].y, d4[j].y) == 1.0f) ? w : 0.0f;
            pot.z += (fmaf(xu2, i4[j].z, d4[j].z) == 1.0f) ? w : 0.0f;
            pot.w += (fmaf(xu3, i4[j].w, d4[j].w) == 1.0f) ? w : 0.0f;
        }
    }

    *reinterpret_cast<float4*>(out + (size_t)bo * L_ + l0) = pot;
}

extern "C" void kernel_launch(void* const* d_in, const int* in_sizes, int n_in,
                              void* d_out, int out_size) {
    const float* x      = (const float*)d_in[0];
    const float* weight = (const float*)d_in[1];
    const float* trace  = (const float*)d_in[2];
    const float* delay  = (const float*)d_in[3];
    const float* dinit  = (const float*)d_in[4];
    const float* alpha  = (const float*)d_in[5];
    const float* tau    = (const float*)d_in[6];
    const float* dt     = (const float*)d_in[7];
    float* out = (float*)d_out;

    dim3 grid(L_ / (ROWS_PER_BLK * WO_), B_ * COUT_);   // (4, 128)
    conv2d_expdelay_kernel<<<grid, THREADS>>>(x, weight, trace, delay, dinit,
                                              alpha, tau, dt, out);
}